// round 1
// baseline (speedup 1.0000x reference)
#include <cuda_runtime.h>
#include <math.h>

#define N_NODES 50000
#define E_EDGES 400000
#define FSZ 256
#define H 8
#define D 64
#define HD 512          // H*D
#define BSZ 1024
#define NH 8
#define ECAP 65536

// ---------------- scratch (device globals; reset each launch) ----------------
__device__ int   g_node_slot[N_NODES];   // canonical b per selected node, INT_MAX else
__device__ int   g_edge_cnt;
__device__ int   g_esrc[ECAP];
__device__ int   g_eslot[ECAP];
__device__ float g_WL[FSZ * H];
__device__ float g_WR[FSZ * H];
__device__ float g_er[BSZ * H];
__device__ float g_m[BSZ * H];
__device__ float g_denom[BSZ * H];
__device__ float g_score[ECAP * H];      // scores, then overwritten with exp()
__device__ float g_rst[BSZ * HD];        // softmax-weighted message sums
__device__ float g_xpre[BSZ * HD];       // rst + res + bias (pre-LN)
__device__ float g_x[BSZ * HD];          // post-LN (MHA input / residual)
__device__ float g_q[BSZ * H * HD];
__device__ float g_k[BSZ * H * HD];
__device__ float g_v[BSZ * H * HD];
__device__ float g_o[BSZ * H * HD];

__device__ __forceinline__ void atomicMaxF(float* addr, float val) {
    int* ai = (int*)addr;
    int old = *ai;
    while (__int_as_float(old) < val) {
        int assumed = old;
        old = atomicCAS(ai, assumed, __float_as_int(val));
        if (old == assumed) break;
    }
}

// ---------------- 1. init scratch ----------------
__global__ void k_init() {
    int i = blockIdx.x * blockDim.x + threadIdx.x;
    int stride = gridDim.x * blockDim.x;
    for (; i < BSZ * HD; i += stride) {
        if (i < N_NODES) g_node_slot[i] = 0x7fffffff;
        if (i < BSZ * H) { g_m[i] = -INFINITY; g_denom[i] = 0.f; }
        g_rst[i] = 0.f;
        if (i == 0) g_edge_cnt = 0;
    }
}

// ---------------- 2. fold attn_l/attn_r into gat_fc_w: WL/WR [FS,H] ----------------
__global__ void k_prep(const float* __restrict__ fcw,
                       const float* __restrict__ al,
                       const float* __restrict__ ar) {
    int idx = blockIdx.x * blockDim.x + threadIdx.x;
    if (idx >= FSZ * H) return;
    int f = idx >> 3, h = idx & 7;
    float wl = 0.f, wr = 0.f;
    #pragma unroll 8
    for (int d = 0; d < D; d++) {
        float w = fcw[f * HD + h * D + d];
        wl += w * al[h * D + d];
        wr += w * ar[h * D + d];
    }
    g_WL[f * H + h] = wl;
    g_WR[f * H + h] = wr;
}

// ---------------- 3. mark selected nodes (canonical slot = min b) ----------------
__global__ void k_scatter(const int* __restrict__ url) {
    int b = blockIdx.x * blockDim.x + threadIdx.x;
    if (b < BSZ) atomicMin(&g_node_slot[url[b] - 1], b);
}

// ---------------- 4. compact edges with dst in selected set ----------------
__global__ void k_filter(const int* __restrict__ src, const int* __restrict__ dst) {
    int i = blockIdx.x * blockDim.x + threadIdx.x;
    int stride = gridDim.x * blockDim.x;
    for (; i < E_EDGES; i += stride) {
        int s = g_node_slot[dst[i]];
        if (s != 0x7fffffff) {
            int idx = atomicAdd(&g_edge_cnt, 1);
            if (idx < ECAP) { g_esrc[idx] = src[i]; g_eslot[idx] = s; }
        }
    }
}

// ---------------- 5. er[b,h] = features[url[b]-1] @ WR ----------------
__global__ void k_er(const float* __restrict__ feat, const int* __restrict__ url) {
    int b = blockIdx.x;
    __shared__ float sf[FSZ];
    int t = threadIdx.x;
    int node = url[b] - 1;
    sf[t] = feat[node * FSZ + t];
    __syncthreads();
    int h = t >> 5, lane = t & 31;
    float acc = 0.f;
    for (int f = lane; f < FSZ; f += 32) acc += sf[f] * g_WR[f * H + h];
    #pragma unroll
    for (int o = 16; o; o >>= 1) acc += __shfl_xor_sync(0xffffffffu, acc, o);
    if (lane == 0) g_er[b * H + h] = acc;
}

// ---------------- 6. per-edge scores + segment max (one warp per edge) ----------------
__global__ void k_score(const float* __restrict__ feat) {
    int cnt = g_edge_cnt; if (cnt > ECAP) cnt = ECAP;
    int lane = threadIdx.x & 31;
    int w  = (blockIdx.x * blockDim.x + threadIdx.x) >> 5;
    int nw = (gridDim.x * blockDim.x) >> 5;
    for (int e = w; e < cnt; e += nw) {
        const float* F = feat + (long)g_esrc[e] * FSZ;
        int slot = g_eslot[e];
        float acc[H] = {};
        for (int f = lane; f < FSZ; f += 32) {
            float fv = F[f];
            #pragma unroll
            for (int h = 0; h < H; h++) acc[h] += fv * g_WL[f * H + h];
        }
        #pragma unroll
        for (int o = 16; o; o >>= 1)
            #pragma unroll
            for (int h = 0; h < H; h++)
                acc[h] += __shfl_xor_sync(0xffffffffu, acc[h], o);
        if (lane == 0) {
            #pragma unroll
            for (int h = 0; h < H; h++) {
                float sc = acc[h] + g_er[slot * H + h];
                sc = sc > 0.f ? sc : 0.2f * sc;          // leaky relu
                g_score[e * H + h] = sc;
                atomicMaxF(&g_m[slot * H + h], sc);
            }
        }
    }
}

// ---------------- 7. exp + segment sum ----------------
__global__ void k_exp() {
    int cnt = g_edge_cnt; if (cnt > ECAP) cnt = ECAP;
    int total = cnt * H;
    int i = blockIdx.x * blockDim.x + threadIdx.x;
    int stride = gridDim.x * blockDim.x;
    for (; i < total; i += stride) {
        int e = i >> 3, h = i & 7;
        int slot = g_eslot[e];
        float ex = __expf(g_score[i] - g_m[slot * H + h]);
        g_score[i] = ex;
        atomicAdd(&g_denom[slot * H + h], ex);
    }
}

// ---------------- 8. fused edge-feature GEMM + weighted scatter ----------------
// tile: 32 edges x 64 cols, K=256.  grid (8 col-tiles, ECAP/32 edge-tiles)
__global__ void k_msg(const float* __restrict__ feat, const float* __restrict__ fcw) {
    int cnt = g_edge_cnt; if (cnt > ECAP) cnt = ECAP;
    int e0 = blockIdx.y * 32;
    if (e0 >= cnt) return;
    int c0 = blockIdx.x * 64;
    int hcol = c0 >> 6;                      // one head per col tile
    __shared__ float sA[32][FSZ];
    __shared__ float sB[32][65];
    __shared__ int ssrc[32], sslot[32];
    int t = threadIdx.x;
    if (t < 32) {
        int e = e0 + t;
        ssrc[t]  = (e < cnt) ? g_esrc[e]  : 0;
        sslot[t] = (e < cnt) ? g_eslot[e] : 0;
    }
    __syncthreads();
    for (int i = t; i < 32 * FSZ; i += 256) {
        int r = i >> 8, k = i & 255;
        sA[r][k] = feat[(long)ssrc[r] * FSZ + k];
    }
    int tx = t & 15, ty = t >> 4;
    float acc[2][4] = {};
    for (int k0 = 0; k0 < FSZ; k0 += 32) {
        __syncthreads();
        for (int i = t; i < 32 * 64; i += 256) {
            int k = i >> 6, c = i & 63;
            sB[k][c] = fcw[(k0 + k) * HD + c0 + c];
        }
        __syncthreads();
        #pragma unroll
        for (int kk = 0; kk < 32; kk++) {
            float a0 = sA[ty * 2][k0 + kk], a1 = sA[ty * 2 + 1][k0 + kk];
            float b0 = sB[kk][tx * 4], b1 = sB[kk][tx * 4 + 1];
            float b2 = sB[kk][tx * 4 + 2], b3 = sB[kk][tx * 4 + 3];
            acc[0][0] += a0 * b0; acc[0][1] += a0 * b1; acc[0][2] += a0 * b2; acc[0][3] += a0 * b3;
            acc[1][0] += a1 * b0; acc[1][1] += a1 * b1; acc[1][2] += a1 * b2; acc[1][3] += a1 * b3;
        }
    }
    #pragma unroll
    for (int rr = 0; rr < 2; rr++) {
        int r = ty * 2 + rr;
        int e = e0 + r;
        if (e >= cnt) continue;
        int slot = sslot[r];
        float aw = g_score[e * H + hcol] / fmaxf(g_denom[slot * H + hcol], 1e-20f);
        #pragma unroll
        for (int cc = 0; cc < 4; cc++)
            atomicAdd(&g_rst[slot * HD + c0 + tx * 4 + cc], acc[rr][cc] * aw);
    }
}

// ---------------- 9. residual GEMM [B,256]x[256,512] + gather rst + bias ----------------
__global__ void k_res(const float* __restrict__ feat, const float* __restrict__ resw,
                      const int* __restrict__ url, const float* __restrict__ bias) {
    int r0 = blockIdx.y * 32, c0 = blockIdx.x * 64;
    __shared__ float sA[32][FSZ];
    __shared__ float sB[32][65];
    __shared__ int snode[32];
    int t = threadIdx.x;
    if (t < 32) snode[t] = url[r0 + t] - 1;
    __syncthreads();
    for (int i = t; i < 32 * FSZ; i += 256) {
        int r = i >> 8, k = i & 255;
        sA[r][k] = feat[(long)snode[r] * FSZ + k];
    }
    int tx = t & 15, ty = t >> 4;
    float acc[2][4] = {};
    for (int k0 = 0; k0 < FSZ; k0 += 32) {
        __syncthreads();
        for (int i = t; i < 32 * 64; i += 256) {
            int k = i >> 6, c = i & 63;
            sB[k][c] = resw[(k0 + k) * HD + c0 + c];
        }
        __syncthreads();
        #pragma unroll
        for (int kk = 0; kk < 32; kk++) {
            float a0 = sA[ty * 2][k0 + kk], a1 = sA[ty * 2 + 1][k0 + kk];
            float b0 = sB[kk][tx * 4], b1 = sB[kk][tx * 4 + 1];
            float b2 = sB[kk][tx * 4 + 2], b3 = sB[kk][tx * 4 + 3];
            acc[0][0] += a0 * b0; acc[0][1] += a0 * b1; acc[0][2] += a0 * b2; acc[0][3] += a0 * b3;
            acc[1][0] += a1 * b0; acc[1][1] += a1 * b1; acc[1][2] += a1 * b2; acc[1][3] += a1 * b3;
        }
    }
    #pragma unroll
    for (int rr = 0; rr < 2; rr++) {
        int r = ty * 2 + rr;
        int slot = g_node_slot[snode[r]];
        #pragma unroll
        for (int cc = 0; cc < 4; cc++) {
            int c = c0 + tx * 4 + cc;
            g_xpre[(r0 + r) * HD + c] = acc[rr][cc] + g_rst[slot * HD + c] + bias[c];
        }
    }
}

// ---------------- 10. LayerNorm over D (warp per (b,h) row) ----------------
__global__ void k_ln(const float* __restrict__ lg, const float* __restrict__ lb) {
    int w = threadIdx.x >> 5, lane = threadIdx.x & 31;
    int row = blockIdx.x * 8 + w;
    const float* src = g_xpre + row * D;
    float v0 = src[lane], v1 = src[lane + 32];
    float s = v0 + v1, ss = v0 * v0 + v1 * v1;
    #pragma unroll
    for (int o = 16; o; o >>= 1) {
        s  += __shfl_xor_sync(0xffffffffu, s, o);
        ss += __shfl_xor_sync(0xffffffffu, ss, o);
    }
    float mu = s * (1.f / D), var = ss * (1.f / D) - mu * mu;
    float rs = rsqrtf(var + 1e-6f);
    g_x[row * D + lane]      = (v0 - mu) * rs * lg[lane] + lb[lane];
    g_x[row * D + lane + 32] = (v1 - mu) * rs * lg[lane + 32] + lb[lane + 32];
}

// ---------------- 11. qkv GEMM [8192,64]x[64,512] (z selects q/k/v) ----------------
__global__ void k_qkv(const float* __restrict__ wq, const float* __restrict__ wk,
                      const float* __restrict__ wv) {
    const float* W = blockIdx.z == 0 ? wq : (blockIdx.z == 1 ? wk : wv);
    float* O = blockIdx.z == 0 ? g_q : (blockIdx.z == 1 ? g_k : g_v);
    __shared__ float sA[32][65];
    __shared__ float sB[64][65];
    int r0 = blockIdx.y * 32, c0 = blockIdx.x * 64, t = threadIdx.x;
    for (int i = t; i < 32 * 64; i += 256) {
        int r = i >> 6, k = i & 63;
        sA[r][k] = g_x[(r0 + r) * D + k];
    }
    for (int i = t; i < 64 * 64; i += 256) {
        int k = i >> 6, c = i & 63;
        sB[k][c] = W[k * HD + c0 + c];
    }
    __syncthreads();
    int tx = t & 15, ty = t >> 4;
    float acc[2][4] = {};
    #pragma unroll 8
    for (int k = 0; k < 64; k++) {
        float a0 = sA[ty * 2][k], a1 = sA[ty * 2 + 1][k];
        float b0 = sB[k][tx * 4], b1 = sB[k][tx * 4 + 1];
        float b2 = sB[k][tx * 4 + 2], b3 = sB[k][tx * 4 + 3];
        acc[0][0] += a0 * b0; acc[0][1] += a0 * b1; acc[0][2] += a0 * b2; acc[0][3] += a0 * b3;
        acc[1][0] += a1 * b0; acc[1][1] += a1 * b1; acc[1][2] += a1 * b2; acc[1][3] += a1 * b3;
    }
    #pragma unroll
    for (int rr = 0; rr < 2; rr++)
        #pragma unroll
        for (int cc = 0; cc < 4; cc++)
            O[(r0 + ty * 2 + rr) * HD + c0 + tx * 4 + cc] = acc[rr][cc];
}

// ---------------- 12. attention per (b, nh): 8x8 scores, softmax, o = attn@v ----------------
__global__ void k_attn() {
    int nh = blockIdx.x, b = blockIdx.y;
    __shared__ float sq[8][65], sk[8][65], sv[8][65], sat[8][9];
    int t = threadIdx.x;
    for (int i = t; i < 8 * D; i += 64) {
        int s = i >> 6, d = i & 63;
        int idx = (b * H + s) * HD + nh * D + d;
        sq[s][d] = g_q[idx]; sk[s][d] = g_k[idx]; sv[s][d] = g_v[idx];
    }
    __syncthreads();
    {
        int qi = t >> 3, ki = t & 7;
        float a = 0.f;
        #pragma unroll 16
        for (int d = 0; d < D; d++) a += sq[qi][d] * sk[ki][d];
        sat[qi][ki] = a * 0.125f;
    }
    __syncthreads();
    if (t < 8) {
        float mx = -1e30f;
        #pragma unroll
        for (int k = 0; k < 8; k++) mx = fmaxf(mx, sat[t][k]);
        float s = 0.f;
        #pragma unroll
        for (int k = 0; k < 8; k++) { float e = __expf(sat[t][k] - mx); s += e; sat[t][k] = e; }
        float inv = 1.f / s;
        #pragma unroll
        for (int k = 0; k < 8; k++) sat[t][k] *= inv;
    }
    __syncthreads();
    {
        int d = t;
        #pragma unroll
        for (int qi = 0; qi < 8; qi++) {
            float a = 0.f;
            #pragma unroll
            for (int k = 0; k < 8; k++) a += sat[qi][k] * sv[k][d];
            g_o[(b * H + qi) * HD + nh * D + d] = a;
        }
    }
}

// ---------------- 13. fc GEMM + residual + LN + pool + classify -> logits ----------------
// 64 rows (= 8 b's) per block, N=64 full width
__global__ void k_fc(const float* __restrict__ fcw, const float* __restrict__ fcb,
                     const float* __restrict__ mlg, const float* __restrict__ mlb,
                     const float* __restrict__ ow,  const float* __restrict__ ob,
                     float* __restrict__ out) {
    __shared__ float sA[64][65];
    __shared__ float sB[64][65];
    __shared__ float spool[8][64];
    int r0 = blockIdx.x * 64, t = threadIdx.x, tx = t & 15, ty = t >> 4;
    float acc[4][4] = {};
    for (int k0 = 0; k0 < HD; k0 += 64) {
        __syncthreads();
        for (int i = t; i < 64 * 64; i += 256) {
            int r = i >> 6, k = i & 63;
            sA[r][k] = g_o[(r0 + r) * HD + k0 + k];
        }
        for (int i = t; i < 64 * 64; i += 256) {
            int k = i >> 6, c = i & 63;
            sB[k][c] = fcw[(k0 + k) * D + c];
        }
        __syncthreads();
        #pragma unroll 8
        for (int kk = 0; kk < 64; kk++) {
            float a0 = sA[ty * 4][kk], a1 = sA[ty * 4 + 1][kk];
            float a2 = sA[ty * 4 + 2][kk], a3 = sA[ty * 4 + 3][kk];
            float b0 = sB[kk][tx * 4], b1 = sB[kk][tx * 4 + 1];
            float b2 = sB[kk][tx * 4 + 2], b3 = sB[kk][tx * 4 + 3];
            acc[0][0] += a0 * b0; acc[0][1] += a0 * b1; acc[0][2] += a0 * b2; acc[0][3] += a0 * b3;
            acc[1][0] += a1 * b0; acc[1][1] += a1 * b1; acc[1][2] += a1 * b2; acc[1][3] += a1 * b3;
            acc[2][0] += a2 * b0; acc[2][1] += a2 * b1; acc[2][2] += a2 * b2; acc[2][3] += a2 * b3;
            acc[3][0] += a3 * b0; acc[3][1] += a3 * b1; acc[3][2] += a3 * b2; acc[3][3] += a3 * b3;
        }
    }
    __syncthreads();
    #pragma unroll
    for (int rr = 0; rr < 4; rr++)
        #pragma unroll
        for (int cc = 0; cc < 4; cc++) {
            int r = ty * 4 + rr, c = tx * 4 + cc;
            sA[r][c] = acc[rr][cc] + fcb[c] + g_x[(r0 + r) * D + c];
        }
    __syncthreads();
    // LN per row
    int w = t >> 5, lane = t & 31;
    for (int i = 0; i < 8; i++) {
        int r = w * 8 + i;
        float v0 = sA[r][lane], v1 = sA[r][lane + 32];
        float s = v0 + v1, ss = v0 * v0 + v1 * v1;
        #pragma unroll
        for (int o = 16; o; o >>= 1) {
            s  += __shfl_xor_sync(0xffffffffu, s, o);
            ss += __shfl_xor_sync(0xffffffffu, ss, o);
        }
        float mu = s * (1.f / D), var = ss * (1.f / D) - mu * mu;
        float rs = rsqrtf(var + 1e-6f);
        sA[r][lane]      = (v0 - mu) * rs * mlg[lane] + mlb[lane];
        sA[r][lane + 32] = (v1 - mu) * rs * mlg[lane + 32] + mlb[lane + 32];
    }
    __syncthreads();
    // pool over the 8 gat heads
    for (int i = t; i < 8 * D; i += 256) {
        int bi = i >> 6, c = i & 63;
        float p = 0.f;
        #pragma unroll
        for (int h = 0; h < H; h++) p += sA[bi * 8 + h][c];
        spool[bi][c] = p;
    }
    __syncthreads();
    if (t < 16) {
        int bi = t >> 1, cls = t & 1;
        float a = ob[cls];
        #pragma unroll 8
        for (int c = 0; c < D; c++) a += spool[bi][c] * ow[c * 2 + cls];
        out[(r0 / 8 + bi) * 2 + cls] = a;
    }
}

// ---------------- launch ----------------
extern "C" void kernel_launch(void* const* d_in, const int* in_sizes, int n_in,
                              void* d_out, int out_size) {
    const float* features  = (const float*)d_in[0];
    const int*   src       = (const int*)  d_in[1];
    const int*   dst       = (const int*)  d_in[2];
    const int*   url       = (const int*)  d_in[3];
    const float* gat_fc_w  = (const float*)d_in[4];
    const float* attn_l    = (const float*)d_in[5];
    const float* attn_r    = (const float*)d_in[6];
    const float* gat_res_w = (const float*)d_in[7];
    const float* gat_bias  = (const float*)d_in[8];
    const float* ln_g      = (const float*)d_in[9];
    const float* ln_b      = (const float*)d_in[10];
    const float* wq        = (const float*)d_in[11];
    const float* wk        = (const float*)d_in[12];
    const float* wv        = (const float*)d_in[13];
    const float* fc_w      = (const float*)d_in[14];
    const float* fc_b      = (const float*)d_in[15];
    const float* mha_ln_g  = (const float*)d_in[16];
    const float* mha_ln_b  = (const float*)d_in[17];
    const float* out_w     = (const float*)d_in[18];
    const float* out_b     = (const float*)d_in[19];
    float* out = (float*)d_out;

    k_init<<<2048, 256>>>();
    k_prep<<<8, 256>>>(gat_fc_w, attn_l, attn_r);
    k_scatter<<<4, 256>>>(url);
    k_filter<<<512, 256>>>(src, dst);
    k_er<<<BSZ, 256>>>(features, url);
    k_score<<<256, 256>>>(features);
    k_exp<<<256, 256>>>();
    k_msg<<<dim3(8, ECAP / 32), 256>>>(features, gat_fc_w);
    k_res<<<dim3(8, BSZ / 32), 256>>>(features, gat_res_w, url, gat_bias);
    k_ln<<<BSZ, 256>>>(ln_g, ln_b);
    k_qkv<<<dim3(8, BSZ * H / 32, 3), 256>>>(wq, wk, wv);
    k_attn<<<dim3(NH, BSZ), 64>>>();
    k_fc<<<BSZ * H / 64, 256>>>(fc_w, fc_b, mha_ln_g, mha_ln_b, out_w, out_b, out);
}

// round 3
// speedup vs baseline: 1.6173x; 1.6173x over previous
#include <cuda_runtime.h>
#include <math.h>

#define N_NODES 50000
#define E_EDGES 400000
#define FSZ 256
#define H 8
#define D 64
#define HD 512
#define BSZ 1024
#define NH 8
#define DEG 64          // per-slot edge cap (Poisson(8); P(>64) ~ 1e-30)

// ---------------- scratch ----------------
__device__ int   g_node_slot[N_NODES];
__device__ int   g_slot_cnt[BSZ];
__device__ int   g_bsrc[BSZ * DEG];
__device__ float g_WL[FSZ * H];
__device__ float g_WR[FSZ * H];
__device__ float g_agg[BSZ * H * FSZ];   // aggregated raw features per (slot, head)
__device__ float g_x[BSZ * HD];          // post-LN GAT output
__device__ float g_q[BSZ * H * HD];
__device__ float g_k[BSZ * H * HD];
__device__ float g_v[BSZ * H * HD];
__device__ float g_o[BSZ * H * HD];

// ---------------- 1. init + fold attn vectors into fc weight ----------------
__global__ void k_init(const float* __restrict__ fcw,
                       const float* __restrict__ al,
                       const float* __restrict__ ar) {
    int i = blockIdx.x * blockDim.x + threadIdx.x;
    if (i < N_NODES) g_node_slot[i] = 0x7fffffff;
    if (i < BSZ) g_slot_cnt[i] = 0;
    if (i < FSZ * H) {
        int f = i >> 3, h = i & 7;
        float wl = 0.f, wr = 0.f;
        #pragma unroll 8
        for (int d = 0; d < D; d++) {
            float w = fcw[f * HD + h * D + d];
            wl += w * al[h * D + d];
            wr += w * ar[h * D + d];
        }
        g_WL[f * H + h] = wl;
        g_WR[f * H + h] = wr;
    }
}

// ---------------- 2. mark selected nodes (canonical slot = min b) ----------------
__global__ void k_scatter(const int* __restrict__ url) {
    int b = blockIdx.x * blockDim.x + threadIdx.x;
    if (b < BSZ) atomicMin(&g_node_slot[url[b] - 1], b);
}

// ---------------- 3. bucket edges by destination slot ----------------
__global__ void k_filter(const int* __restrict__ src, const int* __restrict__ dst) {
    int i4 = blockIdx.x * blockDim.x + threadIdx.x;
    if (i4 >= E_EDGES / 4) return;
    int4 dv = ((const int4*)dst)[i4];
    int4 sv = ((const int4*)src)[i4];
    int d[4] = {dv.x, dv.y, dv.z, dv.w};
    int s4[4] = {sv.x, sv.y, sv.z, sv.w};
    #pragma unroll
    for (int j = 0; j < 4; j++) {
        int s = g_node_slot[d[j]];
        if (s != 0x7fffffff) {
            int pos = atomicAdd(&g_slot_cnt[s], 1);
            if (pos < DEG) g_bsrc[s * DEG + pos] = s4[j];
        }
    }
}

// ---------------- 4. fused per-slot: scores + leaky + softmax + feature agg ----------------
__global__ void k_gat(const float* __restrict__ feat, const int* __restrict__ url) {
    int b = blockIdx.x;
    int t = threadIdx.x, lane = t & 31, w = t >> 5;
    __shared__ float sdst[FSZ];
    __shared__ float ser[H];
    __shared__ float sw[DEG][H];
    __shared__ int ssrc[DEG];
    int cnt = g_slot_cnt[b]; if (cnt > DEG) cnt = DEG;
    int node = url[b] - 1;
    sdst[t] = feat[(long)node * FSZ + t];
    if (t < cnt) ssrc[t] = g_bsrc[b * DEG + t];
    __syncthreads();
    // er[h]: warp w computes head w
    {
        float acc = 0.f;
        for (int f = lane; f < FSZ; f += 32) acc += sdst[f] * g_WR[f * H + w];
        #pragma unroll
        for (int o = 16; o; o >>= 1) acc += __shfl_xor_sync(0xffffffffu, acc, o);
        if (lane == 0) ser[w] = acc;
    }
    __syncthreads();
    // per-edge scores (warp per edge)
    for (int e = w; e < cnt; e += 8) {
        const float* F = feat + (long)ssrc[e] * FSZ;
        float acc[H] = {};
        for (int f = lane; f < FSZ; f += 32) {
            float fv = F[f];
            #pragma unroll
            for (int h = 0; h < H; h++) acc[h] += fv * g_WL[f * H + h];
        }
        #pragma unroll
        for (int o = 16; o; o >>= 1)
            #pragma unroll
            for (int h = 0; h < H; h++)
                acc[h] += __shfl_xor_sync(0xffffffffu, acc[h], o);
        if (lane == 0) {
            #pragma unroll
            for (int h = 0; h < H; h++) {
                float s = acc[h] + ser[h];
                sw[e][h] = s > 0.f ? s : 0.2f * s;
            }
        }
    }
    __syncthreads();
    // local softmax per head over this slot's edges
    if (t < H) {
        float mx = -1e30f;
        for (int e = 0; e < cnt; e++) mx = fmaxf(mx, sw[e][t]);
        float sum = 0.f;
        for (int e = 0; e < cnt; e++) { float ex = __expf(sw[e][t] - mx); sum += ex; sw[e][t] = ex; }
        float inv = 1.f / fmaxf(sum, 1e-20f);
        for (int e = 0; e < cnt; e++) sw[e][t] *= inv;
    }
    __syncthreads();
    // weighted raw-feature aggregation (each thread owns feature column t)
    float racc[H] = {};
    for (int e = 0; e < cnt; e++) {
        float fv = feat[(long)ssrc[e] * FSZ + t];
        #pragma unroll
        for (int h = 0; h < H; h++) racc[h] += sw[e][h] * fv;
    }
    #pragma unroll
    for (int h = 0; h < H; h++) g_agg[(b * H + h) * FSZ + t] = racc[h];
}

// ---------------- 5. fused dual GEMM (res + agg@W) + bias + LayerNorm ----------------
// tile 64 rows x 64 cols (col tile == head), K=256, 4x4 register blocking
__global__ void k_rst_res(const float* __restrict__ feat, const float* __restrict__ resw,
                          const float* __restrict__ fcw, const int* __restrict__ url,
                          const float* __restrict__ bias,
                          const float* __restrict__ lg, const float* __restrict__ lb) {
    __shared__ float sF[64][33];
    __shared__ float sG[64][33];
    __shared__ float sBr[32][65];
    __shared__ float sBw[32][65];
    __shared__ int snode[64], sslot[64];
    int r0 = blockIdx.y * 64, hcol = blockIdx.x, c0 = hcol * 64;
    int t = threadIdx.x, tx = t & 15, ty = t >> 4;
    if (t < 64) {
        int n = url[r0 + t] - 1;
        snode[t] = n;
        sslot[t] = g_node_slot[n];
    }
    __syncthreads();
    float acc[4][4] = {};
    for (int k0 = 0; k0 < FSZ; k0 += 32) {
        for (int i = t; i < 64 * 32; i += 256) {
            int r = i >> 5, k = i & 31;
            sF[r][k] = feat[(long)snode[r] * FSZ + k0 + k];
            sG[r][k] = g_agg[(sslot[r] * H + hcol) * FSZ + k0 + k];
        }
        for (int i = t; i < 32 * 64; i += 256) {
            int k = i >> 6, c = i & 63;
            sBr[k][c] = resw[(k0 + k) * HD + c0 + c];
            sBw[k][c] = fcw[(k0 + k) * HD + c0 + c];
        }
        __syncthreads();
        #pragma unroll 8
        for (int kk = 0; kk < 32; kk++) {
            float af[4], ag[4], br[4], bw[4];
            #pragma unroll
            for (int j = 0; j < 4; j++) { af[j] = sF[ty * 4 + j][kk]; ag[j] = sG[ty * 4 + j][kk]; }
            #pragma unroll
            for (int i = 0; i < 4; i++) { br[i] = sBr[kk][tx * 4 + i]; bw[i] = sBw[kk][tx * 4 + i]; }
            #pragma unroll
            for (int j = 0; j < 4; j++)
                #pragma unroll
                for (int i = 0; i < 4; i++)
                    acc[j][i] += af[j] * br[i] + ag[j] * bw[i];
        }
        __syncthreads();
    }
    // + bias, then LayerNorm per row (row's full D=64 lives in this block's 16 tx lanes)
    #pragma unroll
    for (int j = 0; j < 4; j++) {
        float s = 0.f, ss = 0.f;
        #pragma unroll
        for (int i = 0; i < 4; i++) {
            acc[j][i] += bias[c0 + tx * 4 + i];
            s += acc[j][i]; ss += acc[j][i] * acc[j][i];
        }
        #pragma unroll
        for (int o = 1; o < 16; o <<= 1) {
            s  += __shfl_xor_sync(0xffffffffu, s, o);
            ss += __shfl_xor_sync(0xffffffffu, ss, o);
        }
        float mu = s * (1.f / D), var = ss * (1.f / D) - mu * mu;
        float rs = rsqrtf(var + 1e-6f);
        #pragma unroll
        for (int i = 0; i < 4; i++) {
            int c = tx * 4 + i;
            g_x[(r0 + ty * 4 + j) * HD + c0 + c] = (acc[j][i] - mu) * rs * lg[c] + lb[c];
        }
    }
}

// ---------------- 6. qkv GEMM: [8192,64]x[64,512], A tile shared across q/k/v ----------------
__global__ void k_qkv(const float* __restrict__ wq, const float* __restrict__ wk,
                      const float* __restrict__ wv) {
    __shared__ float sA[64][65];
    __shared__ float sB[64][65];
    int r0 = blockIdx.y * 64, c0 = blockIdx.x * 64;
    int t = threadIdx.x, tx = t & 15, ty = t >> 4;
    for (int i = t; i < 64 * 64; i += 256) {
        int r = i >> 6, k = i & 63;
        sA[r][k] = g_x[(r0 + r) * D + k];
    }
    const float* Ws[3] = {wq, wk, wv};
    float* Os[3] = {g_q, g_k, g_v};
    for (int ws = 0; ws < 3; ws++) {
        __syncthreads();
        const float* W = Ws[ws];
        for (int i = t; i < 64 * 64; i += 256) {
            int k = i >> 6, c = i & 63;
            sB[k][c] = W[k * HD + c0 + c];
        }
        __syncthreads();
        float acc[4][4] = {};
        #pragma unroll 8
        for (int k = 0; k < 64; k++) {
            float a[4], bb[4];
            #pragma unroll
            for (int j = 0; j < 4; j++) a[j] = sA[ty * 4 + j][k];
            #pragma unroll
            for (int i = 0; i < 4; i++) bb[i] = sB[k][tx * 4 + i];
            #pragma unroll
            for (int j = 0; j < 4; j++)
                #pragma unroll
                for (int i = 0; i < 4; i++)
                    acc[j][i] += a[j] * bb[i];
        }
        float* O = Os[ws];
        #pragma unroll
        for (int j = 0; j < 4; j++)
            #pragma unroll
            for (int i = 0; i < 4; i++)
                O[(r0 + ty * 4 + j) * HD + c0 + tx * 4 + i] = acc[j][i];
    }
}

// ---------------- 7. attention per (b, nh) ----------------
__global__ void k_attn() {
    int nh = blockIdx.x, b = blockIdx.y;
    __shared__ float sq[8][65], sk[8][65], sv[8][65], sat[8][9];
    int t = threadIdx.x;
    for (int i = t; i < 8 * D; i += 64) {
        int s = i >> 6, d = i & 63;
        int idx = (b * H + s) * HD + nh * D + d;
        sq[s][d] = g_q[idx]; sk[s][d] = g_k[idx]; sv[s][d] = g_v[idx];
    }
    __syncthreads();
    {
        int qi = t >> 3, ki = t & 7;
        float a = 0.f;
        #pragma unroll 16
        for (int d = 0; d < D; d++) a += sq[qi][d] * sk[ki][d];
        sat[qi][ki] = a * 0.125f;
    }
    __syncthreads();
    if (t < 8) {
        float mx = -1e30f;
        #pragma unroll
        for (int k = 0; k < 8; k++) mx = fmaxf(mx, sat[t][k]);
        float s = 0.f;
        #pragma unroll
        for (int k = 0; k < 8; k++) { float e = __expf(sat[t][k] - mx); s += e; sat[t][k] = e; }
        float inv = 1.f / s;
        #pragma unroll
        for (int k = 0; k < 8; k++) sat[t][k] *= inv;
    }
    __syncthreads();
    {
        int d = t;
        #pragma unroll
        for (int qi = 0; qi < 8; qi++) {
            float a = 0.f;
            #pragma unroll
            for (int k = 0; k < 8; k++) a += sat[qi][k] * sv[k][d];
            g_o[(b * H + qi) * HD + nh * D + d] = a;
        }
    }
}

// ---------------- 8. fc GEMM + residual + LN + pool + classify ----------------
__global__ void k_fc(const float* __restrict__ fcw, const float* __restrict__ fcb,
                     const float* __restrict__ mlg, const float* __restrict__ mlb,
                     const float* __restrict__ ow,  const float* __restrict__ ob,
                     float* __restrict__ out) {
    __shared__ float sA[64][65];
    __shared__ float sB[64][65];
    __shared__ float spool[8][64];
    int r0 = blockIdx.x * 64, t = threadIdx.x, tx = t & 15, ty = t >> 4;
    float acc[4][4] = {};
    for (int k0 = 0; k0 < HD; k0 += 64) {
        __syncthreads();
        for (int i = t; i < 64 * 64; i += 256) {
            int r = i >> 6, k = i & 63;
            sA[r][k] = g_o[(r0 + r) * HD + k0 + k];
        }
        for (int i = t; i < 64 * 64; i += 256) {
            int k = i >> 6, c = i & 63;
            sB[k][c] = fcw[(k0 + k) * D + c];
        }
        __syncthreads();
        #pragma unroll 8
        for (int kk = 0; kk < 64; kk++) {
            float a[4], bb[4];
            #pragma unroll
            for (int j = 0; j < 4; j++) a[j] = sA[ty * 4 + j][kk];
            #pragma unroll
            for (int i = 0; i < 4; i++) bb[i] = sB[kk][tx * 4 + i];
            #pragma unroll
            for (int j = 0; j < 4; j++)
                #pragma unroll
                for (int i = 0; i < 4; i++)
                    acc[j][i] += a[j] * bb[i];
        }
    }
    __syncthreads();
    #pragma unroll
    for (int rr = 0; rr < 4; rr++)
        #pragma unroll
        for (int cc = 0; cc < 4; cc++) {
            int r = ty * 4 + rr, c = tx * 4 + cc;
            sA[r][c] = acc[rr][cc] + fcb[c] + g_x[(r0 + r) * D + c];
        }
    __syncthreads();
    int w = t >> 5, lane = t & 31;
    for (int i = 0; i < 8; i++) {
        int r = w * 8 + i;
        float v0 = sA[r][lane], v1 = sA[r][lane + 32];
        float s = v0 + v1, ss = v0 * v0 + v1 * v1;
        #pragma unroll
        for (int o = 16; o; o >>= 1) {
            s  += __shfl_xor_sync(0xffffffffu, s, o);
            ss += __shfl_xor_sync(0xffffffffu, ss, o);
        }
        float mu = s * (1.f / D), var = ss * (1.f / D) - mu * mu;
        float rs = rsqrtf(var + 1e-6f);
        sA[r][lane]      = (v0 - mu) * rs * mlg[lane] + mlb[lane];
        sA[r][lane + 32] = (v1 - mu) * rs * mlg[lane + 32] + mlb[lane + 32];
    }
    __syncthreads();
    for (int i = t; i < 8 * D; i += 256) {
        int bi = i >> 6, c = i & 63;
        float p = 0.f;
        #pragma unroll
        for (int h = 0; h < H; h++) p += sA[bi * 8 + h][c];
        spool[bi][c] = p;
    }
    __syncthreads();
    if (t < 16) {
        int bi = t >> 1, cls = t & 1;
        float a = ob[cls];
        #pragma unroll 8
        for (int c = 0; c < D; c++) a += spool[bi][c] * ow[c * 2 + cls];
        out[(r0 / 8 + bi) * 2 + cls] = a;
    }
}

// ---------------- launch ----------------
extern "C" void kernel_launch(void* const* d_in, const int* in_sizes, int n_in,
                              void* d_out, int out_size) {
    const float* features  = (const float*)d_in[0];
    const int*   src       = (const int*)  d_in[1];
    const int*   dst       = (const int*)  d_in[2];
    const int*   url       = (const int*)  d_in[3];
    const float* gat_fc_w  = (const float*)d_in[4];
    const float* attn_l    = (const float*)d_in[5];
    const float* attn_r    = (const float*)d_in[6];
    const float* gat_res_w = (const float*)d_in[7];
    const float* gat_bias  = (const float*)d_in[8];
    const float* ln_g      = (const float*)d_in[9];
    const float* ln_b      = (const float*)d_in[10];
    const float* wq        = (const float*)d_in[11];
    const float* wk        = (const float*)d_in[12];
    const float* wv        = (const float*)d_in[13];
    const float* fc_w      = (const float*)d_in[14];
    const float* fc_b      = (const float*)d_in[15];
    const float* mha_ln_g  = (const float*)d_in[16];
    const float* mha_ln_b  = (const float*)d_in[17];
    const float* out_w     = (const float*)d_in[18];
    const float* out_b     = (const float*)d_in[19];
    float* out = (float*)d_out;

    k_init<<<(N_NODES + 255) / 256, 256>>>(gat_fc_w, attn_l, attn_r);
    k_scatter<<<4, 256>>>(url);
    k_filter<<<(E_EDGES / 4 + 255) / 256, 256>>>(src, dst);
    k_gat<<<BSZ, 256>>>(features, url);
    k_rst_res<<<dim3(8, BSZ / 64), 256>>>(features, gat_res_w, gat_fc_w, url,
                                          gat_bias, ln_g, ln_b);
    k_qkv<<<dim3(8, BSZ * H / 64), 256>>>(wq, wk, wv);
    k_attn<<<dim3(NH, BSZ), 64>>>();
    k_fc<<<BSZ * H / 64, 256>>>(fc_w, fc_b, mha_ln_g, mha_ln_b, out_w, out_b, out);
}

// round 4
// speedup vs baseline: 1.7104x; 1.0575x over previous
#include <cuda_runtime.h>
#include <math.h>

#define N_NODES 50000
#define E_EDGES 400000
#define FSZ 256
#define H 8
#define D 64
#define HD 512
#define BSZ 1024
#define NH 8
#define DEG 64          // per-slot edge cap (Poisson(8); P(>64) ~ 1e-30)

// ---------------- scratch ----------------
__device__ int   g_node_slot[N_NODES];
__device__ int   g_slot_cnt[BSZ];
__device__ int   g_bsrc[BSZ * DEG];
__device__ float g_WL[H * FSZ];          // TRANSPOSED: [h][f]
__device__ float g_WR[H * FSZ];          // TRANSPOSED: [h][f]
__device__ float g_agg[BSZ * H * FSZ];   // softmax-weighted raw-feature sums per (slot, head)
__device__ float g_x[BSZ * HD];          // post-LN GAT output
__device__ float g_q[BSZ * H * HD];
__device__ float g_k[BSZ * H * HD];
__device__ float g_v[BSZ * H * HD];
__device__ float g_o[BSZ * H * HD];

// ---------------- 1. init + fold attn vectors into fc weight (transposed out) ----------------
__global__ void k_init(const float* __restrict__ fcw,
                       const float* __restrict__ al,
                       const float* __restrict__ ar) {
    int i = blockIdx.x * blockDim.x + threadIdx.x;
    if (i < N_NODES) g_node_slot[i] = 0x7fffffff;
    if (i < BSZ) g_slot_cnt[i] = 0;
    if (i < FSZ * H) {
        int f = i >> 3, h = i & 7;
        float wl = 0.f, wr = 0.f;
        #pragma unroll 8
        for (int d = 0; d < D; d++) {
            float w = fcw[f * HD + h * D + d];
            wl += w * al[h * D + d];
            wr += w * ar[h * D + d];
        }
        g_WL[h * FSZ + f] = wl;
        g_WR[h * FSZ + f] = wr;
    }
}

// ---------------- 2. mark selected nodes (canonical slot = min b) ----------------
__global__ void k_scatter(const int* __restrict__ url) {
    int b = blockIdx.x * blockDim.x + threadIdx.x;
    if (b < BSZ) atomicMin(&g_node_slot[url[b] - 1], b);
}

// ---------------- 3. bucket edges by destination slot ----------------
__global__ void k_filter(const int* __restrict__ src, const int* __restrict__ dst) {
    int i4 = blockIdx.x * blockDim.x + threadIdx.x;
    if (i4 >= E_EDGES / 4) return;
    int4 dv = ((const int4*)dst)[i4];
    int4 sv = ((const int4*)src)[i4];
    int d[4] = {dv.x, dv.y, dv.z, dv.w};
    int s4[4] = {sv.x, sv.y, sv.z, sv.w};
    #pragma unroll
    for (int j = 0; j < 4; j++) {
        int s = g_node_slot[d[j]];
        if (s != 0x7fffffff) {
            int pos = atomicAdd(&g_slot_cnt[s], 1);
            if (pos < DEG) g_bsrc[s * DEG + pos] = s4[j];
        }
    }
}

// ---------------- 4. single-pass online-softmax GAT aggregation ----------------
// One block per slot. Each edge row streamed through smem ONCE (double-buffered).
__global__ void k_gat(const float* __restrict__ feat, const int* __restrict__ url) {
    int b = blockIdx.x;
    int t = threadIdx.x, lane = t & 31, w = t >> 5;
    __shared__ float sWL[H * FSZ];           // 8 KB
    __shared__ float sWR[H * FSZ];           // 8 KB
    __shared__ float buf[2][FSZ];            // 2 KB edge-row double buffer
    __shared__ float sdst[FSZ];
    __shared__ float ser[H];
    __shared__ float sscore[H];
    __shared__ float sfact[H], swt[H];
    __shared__ int   ssrc[DEG];

    int cnt = g_slot_cnt[b]; if (cnt > DEG) cnt = DEG;
    int node = url[b] - 1;

    for (int i = t; i < H * FSZ; i += 256) { sWL[i] = g_WL[i]; sWR[i] = g_WR[i]; }
    sdst[t] = feat[(long)node * FSZ + t];
    if (t < cnt) ssrc[t] = g_bsrc[b * DEG + t];
    __syncthreads();

    // er[h]: warp w computes head w from the staged dst row
    {
        float a = 0.f;
        #pragma unroll
        for (int j = 0; j < 8; j++) a += sdst[lane + 32 * j] * sWR[w * FSZ + lane + 32 * j];
        #pragma unroll
        for (int o = 16; o; o >>= 1) a += __shfl_xor_sync(0xffffffffu, a, o);
        if (lane == 0) ser[w] = a;
    }
    // stage edge row 0
    buf[0][t] = (cnt > 0) ? feat[(long)ssrc[0] * FSZ + t] : 0.f;

    float racc[H] = {};
    float my_m = -1e30f, my_s = 0.f;         // valid for t < H (head = t)
    __syncthreads();

    for (int e = 0; e < cnt; e++) {
        const float* cur = buf[e & 1];
        // prefetch next row into registers (overlaps with score compute)
        float pre = (e + 1 < cnt) ? feat[(long)ssrc[e + 1] * FSZ + t] : 0.f;
        // score for head w (warp-per-head dot from smem)
        float a = 0.f;
        #pragma unroll
        for (int j = 0; j < 8; j++) a += cur[lane + 32 * j] * sWL[w * FSZ + lane + 32 * j];
        #pragma unroll
        for (int o = 16; o; o >>= 1) a += __shfl_xor_sync(0xffffffffu, a, o);
        if (lane == 0) sscore[w] = a;
        __syncthreads();
        // online softmax bookkeeping by 8 owner threads (head = t)
        if (t < H) {
            float sc = sscore[t] + ser[t];
            sc = sc > 0.f ? sc : 0.2f * sc;              // leaky relu
            float nm = fmaxf(my_m, sc);
            float fct = __expf(my_m - nm);
            float we  = __expf(sc - nm);
            my_s = my_s * fct + we;
            my_m = nm;
            sfact[t] = fct; swt[t] = we;
        }
        __syncthreads();
        // aggregate update: 8 FMA per thread
        float fv = cur[t];
        #pragma unroll
        for (int h = 0; h < H; h++) racc[h] = racc[h] * sfact[h] + swt[h] * fv;
        // commit prefetched row into the other buffer
        buf[(e + 1) & 1][t] = pre;
        __syncthreads();
    }
    if (t < H) sfact[t] = 1.f / fmaxf(my_s, 1e-20f);
    __syncthreads();
    #pragma unroll
    for (int h = 0; h < H; h++)
        g_agg[(b * H + h) * FSZ + t] = racc[h] * sfact[h];
}

// ---------------- 5. fused dual GEMM (res + agg@W) + bias + LayerNorm ----------------
__global__ void k_rst_res(const float* __restrict__ feat, const float* __restrict__ resw,
                          const float* __restrict__ fcw, const int* __restrict__ url,
                          const float* __restrict__ bias,
                          const float* __restrict__ lg, const float* __restrict__ lb) {
    __shared__ float sF[64][33];
    __shared__ float sG[64][33];
    __shared__ float sBr[32][65];
    __shared__ float sBw[32][65];
    __shared__ int snode[64], sslot[64];
    int r0 = blockIdx.y * 64, hcol = blockIdx.x, c0 = hcol * 64;
    int t = threadIdx.x, tx = t & 15, ty = t >> 4;
    if (t < 64) {
        int n = url[r0 + t] - 1;
        snode[t] = n;
        sslot[t] = g_node_slot[n];
    }
    __syncthreads();
    float acc[4][4] = {};
    for (int k0 = 0; k0 < FSZ; k0 += 32) {
        for (int i = t; i < 64 * 32; i += 256) {
            int r = i >> 5, k = i & 31;
            sF[r][k] = feat[(long)snode[r] * FSZ + k0 + k];
            sG[r][k] = g_agg[(sslot[r] * H + hcol) * FSZ + k0 + k];
        }
        for (int i = t; i < 32 * 64; i += 256) {
            int k = i >> 6, c = i & 63;
            sBr[k][c] = resw[(k0 + k) * HD + c0 + c];
            sBw[k][c] = fcw[(k0 + k) * HD + c0 + c];
        }
        __syncthreads();
        #pragma unroll 8
        for (int kk = 0; kk < 32; kk++) {
            float af[4], ag[4], br[4], bw[4];
            #pragma unroll
            for (int j = 0; j < 4; j++) { af[j] = sF[ty * 4 + j][kk]; ag[j] = sG[ty * 4 + j][kk]; }
            #pragma unroll
            for (int i = 0; i < 4; i++) { br[i] = sBr[kk][tx * 4 + i]; bw[i] = sBw[kk][tx * 4 + i]; }
            #pragma unroll
            for (int j = 0; j < 4; j++)
                #pragma unroll
                for (int i = 0; i < 4; i++)
                    acc[j][i] += af[j] * br[i] + ag[j] * bw[i];
        }
        __syncthreads();
    }
    #pragma unroll
    for (int j = 0; j < 4; j++) {
        float s = 0.f, ss = 0.f;
        #pragma unroll
        for (int i = 0; i < 4; i++) {
            acc[j][i] += bias[c0 + tx * 4 + i];
            s += acc[j][i]; ss += acc[j][i] * acc[j][i];
        }
        #pragma unroll
        for (int o = 1; o < 16; o <<= 1) {
            s  += __shfl_xor_sync(0xffffffffu, s, o);
            ss += __shfl_xor_sync(0xffffffffu, ss, o);
        }
        float mu = s * (1.f / D), var = ss * (1.f / D) - mu * mu;
        float rs = rsqrtf(var + 1e-6f);
        #pragma unroll
        for (int i = 0; i < 4; i++) {
            int c = tx * 4 + i;
            g_x[(r0 + ty * 4 + j) * HD + c0 + c] = (acc[j][i] - mu) * rs * lg[c] + lb[c];
        }
    }
}

// ---------------- 6. qkv GEMM: [8192,64]x[64,512], A tile shared across q/k/v ----------------
__global__ void k_qkv(const float* __restrict__ wq, const float* __restrict__ wk,
                      const float* __restrict__ wv) {
    __shared__ float sA[64][65];
    __shared__ float sB[64][65];
    int r0 = blockIdx.y * 64, c0 = blockIdx.x * 64;
    int t = threadIdx.x, tx = t & 15, ty = t >> 4;
    for (int i = t; i < 64 * 64; i += 256) {
        int r = i >> 6, k = i & 63;
        sA[r][k] = g_x[(r0 + r) * D + k];
    }
    const float* Ws[3] = {wq, wk, wv};
    float* Os[3] = {g_q, g_k, g_v};
    for (int ws = 0; ws < 3; ws++) {
        __syncthreads();
        const float* W = Ws[ws];
        for (int i = t; i < 64 * 64; i += 256) {
            int k = i >> 6, c = i & 63;
            sB[k][c] = W[k * HD + c0 + c];
        }
        __syncthreads();
        float acc[4][4] = {};
        #pragma unroll 8
        for (int k = 0; k < 64; k++) {
            float a[4], bb[4];
            #pragma unroll
            for (int j = 0; j < 4; j++) a[j] = sA[ty * 4 + j][k];
            #pragma unroll
            for (int i = 0; i < 4; i++) bb[i] = sB[k][tx * 4 + i];
            #pragma unroll
            for (int j = 0; j < 4; j++)
                #pragma unroll
                for (int i = 0; i < 4; i++)
                    acc[j][i] += a[j] * bb[i];
        }
        float* O = Os[ws];
        #pragma unroll
        for (int j = 0; j < 4; j++)
            #pragma unroll
            for (int i = 0; i < 4; i++)
                O[(r0 + ty * 4 + j) * HD + c0 + tx * 4 + i] = acc[j][i];
    }
}

// ---------------- 7. attention: one block per b, warp = MHA head ----------------
__global__ void k_attn() {
    int b = blockIdx.x, t = threadIdx.x, lane = t & 31, w = t >> 5;   // w = nh
    __shared__ float sq[8][516];      // pad 4 -> qi-distinct banks in score phase
    __shared__ float sk[8][516];
    __shared__ float sat[NH][8][9];
    const float* qb = g_q + (long)b * 8 * HD;
    const float* kb = g_k + (long)b * 8 * HD;
    const float* vb = g_v + (long)b * 8 * HD;
    for (int i = t; i < 8 * HD / 4; i += 256) {
        int r = i >> 7, c = (i & 127) * 4;
        *(float4*)&sq[r][c] = *(const float4*)&qb[r * HD + c];
        *(float4*)&sk[r][c] = *(const float4*)&kb[r * HD + c];
    }
    __syncthreads();
    // scores: lane handles pairs p=lane and p+32 -> (qi,ki)
    #pragma unroll
    for (int pp = 0; pp < 2; pp++) {
        int p = lane + pp * 32;
        int qi = p >> 3, ki = p & 7;
        float a = 0.f;
        #pragma unroll
        for (int d = 0; d < 64; d++) a += sq[qi][w * 64 + d] * sk[ki][w * 64 + d];
        sat[w][qi][ki] = a * 0.125f;
    }
    __syncwarp();
    if (lane < 8) {
        float mx = -1e30f;
        #pragma unroll
        for (int k2 = 0; k2 < 8; k2++) mx = fmaxf(mx, sat[w][lane][k2]);
        float s = 0.f;
        #pragma unroll
        for (int k2 = 0; k2 < 8; k2++) { float e = __expf(sat[w][lane][k2] - mx); s += e; sat[w][lane][k2] = e; }
        float inv = 1.f / s;
        #pragma unroll
        for (int k2 = 0; k2 < 8; k2++) sat[w][lane][k2] *= inv;
    }
    __syncwarp();
    // o = attn @ v  (v straight from L2; lane covers d=lane, lane+32)
    #pragma unroll
    for (int pp = 0; pp < 2; pp++) {
        int d = lane + pp * 32;
        float vk[8];
        #pragma unroll
        for (int k2 = 0; k2 < 8; k2++) vk[k2] = vb[k2 * HD + w * 64 + d];
        #pragma unroll
        for (int qi = 0; qi < 8; qi++) {
            float a = 0.f;
            #pragma unroll
            for (int k2 = 0; k2 < 8; k2++) a += sat[w][qi][k2] * vk[k2];
            g_o[((long)b * 8 + qi) * HD + w * 64 + d] = a;
        }
    }
}

// ---------------- 8. fc GEMM + residual + LN + pool + classify ----------------
__global__ void k_fc(const float* __restrict__ fcw, const float* __restrict__ fcb,
                     const float* __restrict__ mlg, const float* __restrict__ mlb,
                     const float* __restrict__ ow,  const float* __restrict__ ob,
                     float* __restrict__ out) {
    __shared__ float sA[64][65];
    __shared__ float sB[64][65];
    __shared__ float spool[8][64];
    int r0 = blockIdx.x * 64, t = threadIdx.x, tx = t & 15, ty = t >> 4;
    float acc[4][4] = {};
    for (int k0 = 0; k0 < HD; k0 += 64) {
        __syncthreads();
        for (int i = t; i < 64 * 64; i += 256) {
            int r = i >> 6, k = i & 63;
            sA[r][k] = g_o[(r0 + r) * HD + k0 + k];
        }
        for (int i = t; i < 64 * 64; i += 256) {
            int k = i >> 6, c = i & 63;
            sB[k][c] = fcw[(k0 + k) * D + c];
        }
        __syncthreads();
        #pragma unroll 8
        for (int kk = 0; kk < 64; kk++) {
            float a[4], bb[4];
            #pragma unroll
            for (int j = 0; j < 4; j++) a[j] = sA[ty * 4 + j][kk];
            #pragma unroll
            for (int i = 0; i < 4; i++) bb[i] = sB[kk][tx * 4 + i];
            #pragma unroll
            for (int j = 0; j < 4; j++)
                #pragma unroll
                for (int i = 0; i < 4; i++)
                    acc[j][i] += a[j] * bb[i];
        }
    }
    __syncthreads();
    #pragma unroll
    for (int rr = 0; rr < 4; rr++)
        #pragma unroll
        for (int cc = 0; cc < 4; cc++) {
            int r = ty * 4 + rr, c = tx * 4 + cc;
            sA[r][c] = acc[rr][cc] + fcb[c] + g_x[(r0 + r) * D + c];
        }
    __syncthreads();
    int w = t >> 5, lane = t & 31;
    for (int i = 0; i < 8; i++) {
        int r = w * 8 + i;
        float v0 = sA[r][lane], v1 = sA[r][lane + 32];
        float s = v0 + v1, ss = v0 * v0 + v1 * v1;
        #pragma unroll
        for (int o = 16; o; o >>= 1) {
            s  += __shfl_xor_sync(0xffffffffu, s, o);
            ss += __shfl_xor_sync(0xffffffffu, ss, o);
        }
        float mu = s * (1.f / D), var = ss * (1.f / D) - mu * mu;
        float rs = rsqrtf(var + 1e-6f);
        sA[r][lane]      = (v0 - mu) * rs * mlg[lane] + mlb[lane];
        sA[r][lane + 32] = (v1 - mu) * rs * mlg[lane + 32] + mlb[lane + 32];
    }
    __syncthreads();
    for (int i = t; i < 8 * D; i += 256) {
        int bi = i >> 6, c = i & 63;
        float p = 0.f;
        #pragma unroll
        for (int h = 0; h < H; h++) p += sA[bi * 8 + h][c];
        spool[bi][c] = p;
    }
    __syncthreads();
    if (t < 16) {
        int bi = t >> 1, cls = t & 1;
        float a = ob[cls];
        #pragma unroll 8
        for (int c = 0; c < D; c++) a += spool[bi][c] * ow[c * 2 + cls];
        out[(r0 / 8 + bi) * 2 + cls] = a;
    }
}

// ---------------- launch ----------------
extern "C" void kernel_launch(void* const* d_in, const int* in_sizes, int n_in,
                              void* d_out, int out_size) {
    const float* features  = (const float*)d_in[0];
    const int*   src       = (const int*)  d_in[1];
    const int*   dst       = (const int*)  d_in[2];
    const int*   url       = (const int*)  d_in[3];
    const float* gat_fc_w  = (const float*)d_in[4];
    const float* attn_l    = (const float*)d_in[5];
    const float* attn_r    = (const float*)d_in[6];
    const float* gat_res_w = (const float*)d_in[7];
    const float* gat_bias  = (const float*)d_in[8];
    const float* ln_g      = (const float*)d_in[9];
    const float* ln_b      = (const float*)d_in[10];
    const float* wq        = (const float*)d_in[11];
    const float* wk        = (const float*)d_in[12];
    const float* wv        = (const float*)d_in[13];
    const float* fc_w      = (const float*)d_in[14];
    const float* fc_b      = (const float*)d_in[15];
    const float* mha_ln_g  = (const float*)d_in[16];
    const float* mha_ln_b  = (const float*)d_in[17];
    const float* out_w     = (const float*)d_in[18];
    const float* out_b     = (const float*)d_in[19];
    float* out = (float*)d_out;

    k_init<<<(N_NODES + 255) / 256, 256>>>(gat_fc_w, attn_l, attn_r);
    k_scatter<<<4, 256>>>(url);
    k_filter<<<(E_EDGES / 4 + 255) / 256, 256>>>(src, dst);
    k_gat<<<BSZ, 256>>>(features, url);
    k_rst_res<<<dim3(8, BSZ / 64), 256>>>(features, gat_res_w, gat_fc_w, url,
                                          gat_bias, ln_g, ln_b);
    k_qkv<<<dim3(8, BSZ * H / 64), 256>>>(wq, wk, wv);
    k_attn<<<BSZ, 256>>>();
    k_fc<<<BSZ * H / 64, 256>>>(fc_w, fc_b, mha_ln_g, mha_ln_b, out_w, out_b, out);
}

// round 5
// speedup vs baseline: 2.3820x; 1.3927x over previous
#include <cuda_runtime.h>
#include <math.h>

#define N_NODES 50000
#define E_EDGES 400000
#define FSZ 256
#define H 8
#define D 64
#define HD 512
#define BSZ 1024
#define NH 8
#define DEG 64          // per-slot edge cap (Poisson(8); P(>64) ~ 1e-30)

// ---------------- scratch ----------------
__device__ int   g_node_slot[N_NODES];
__device__ int   g_slot_cnt[BSZ];
__device__ int   g_bsrc[BSZ * DEG];
__device__ float g_WL[H * FSZ];          // [h][f]
__device__ float g_WR[H * FSZ];          // [h][f]
__device__ float g_agg[BSZ * H * FSZ];   // softmax-weighted raw-feature sums per (slot, head)
__device__ float g_x[BSZ * HD];          // post-LN GAT output == [8192][64] rows (b*8+s)
__device__ float g_MZ[D * 1024];         // [k][ 0..511 = M_cat (Wq Wk^T/8), 512..1023 = Wvf_cat ]
__device__ float g_yz[BSZ * 8 * 1024];   // per row: y | z

// ---------------- 1. init + fold attn vectors into fc weight ----------------
__global__ void k_init(const float* __restrict__ fcw,
                       const float* __restrict__ al,
                       const float* __restrict__ ar) {
    int i = blockIdx.x * blockDim.x + threadIdx.x;
    if (i < N_NODES) g_node_slot[i] = 0x7fffffff;
    if (i < BSZ) g_slot_cnt[i] = 0;
    if (i < FSZ * H) {
        int f = i >> 3, h = i & 7;
        float wl = 0.f, wr = 0.f;
        #pragma unroll 8
        for (int d = 0; d < D; d++) {
            float w = fcw[f * HD + h * D + d];
            wl += w * al[h * D + d];
            wr += w * ar[h * D + d];
        }
        g_WL[h * FSZ + f] = wl;
        g_WR[h * FSZ + f] = wr;
    }
}

// ---------------- 2. mark selected nodes ----------------
__global__ void k_scatter(const int* __restrict__ url) {
    int b = blockIdx.x * blockDim.x + threadIdx.x;
    if (b < BSZ) atomicMin(&g_node_slot[url[b] - 1], b);
}

// ---------------- 3. bucket edges by destination slot ----------------
__global__ void k_filter(const int* __restrict__ src, const int* __restrict__ dst) {
    int i4 = blockIdx.x * blockDim.x + threadIdx.x;
    if (i4 >= E_EDGES / 4) return;
    int4 dv = ((const int4*)dst)[i4];
    int4 sv = ((const int4*)src)[i4];
    int d[4] = {dv.x, dv.y, dv.z, dv.w};
    int s4[4] = {sv.x, sv.y, sv.z, sv.w};
    #pragma unroll
    for (int j = 0; j < 4; j++) {
        int s = g_node_slot[d[j]];
        if (s != 0x7fffffff) {
            int pos = atomicAdd(&g_slot_cnt[s], 1);
            if (pos < DEG) g_bsrc[s * DEG + pos] = s4[j];
        }
    }
}

// ---------------- 4. single-pass online-softmax GAT aggregation ----------------
__global__ void k_gat(const float* __restrict__ feat, const int* __restrict__ url) {
    int b = blockIdx.x;
    int t = threadIdx.x, lane = t & 31, w = t >> 5;
    __shared__ float sWL[H * FSZ];
    __shared__ float sWR[H * FSZ];
    __shared__ float buf[2][FSZ];
    __shared__ float sdst[FSZ];
    __shared__ float ser[H];
    __shared__ float sscore[H];
    __shared__ float sfact[H], swt[H];
    __shared__ int   ssrc[DEG];

    int cnt = g_slot_cnt[b]; if (cnt > DEG) cnt = DEG;
    int node = url[b] - 1;

    for (int i = t; i < H * FSZ; i += 256) { sWL[i] = g_WL[i]; sWR[i] = g_WR[i]; }
    sdst[t] = feat[(long)node * FSZ + t];
    if (t < cnt) ssrc[t] = g_bsrc[b * DEG + t];
    __syncthreads();

    {
        float a = 0.f;
        #pragma unroll
        for (int j = 0; j < 8; j++) a += sdst[lane + 32 * j] * sWR[w * FSZ + lane + 32 * j];
        #pragma unroll
        for (int o = 16; o; o >>= 1) a += __shfl_xor_sync(0xffffffffu, a, o);
        if (lane == 0) ser[w] = a;
    }
    buf[0][t] = (cnt > 0) ? feat[(long)ssrc[0] * FSZ + t] : 0.f;

    float racc[H] = {};
    float my_m = -1e30f, my_s = 0.f;
    __syncthreads();

    for (int e = 0; e < cnt; e++) {
        const float* cur = buf[e & 1];
        float pre = (e + 1 < cnt) ? feat[(long)ssrc[e + 1] * FSZ + t] : 0.f;
        float a = 0.f;
        #pragma unroll
        for (int j = 0; j < 8; j++) a += cur[lane + 32 * j] * sWL[w * FSZ + lane + 32 * j];
        #pragma unroll
        for (int o = 16; o; o >>= 1) a += __shfl_xor_sync(0xffffffffu, a, o);
        if (lane == 0) sscore[w] = a;
        __syncthreads();
        if (t < H) {
            float sc = sscore[t] + ser[t];
            sc = sc > 0.f ? sc : 0.2f * sc;
            float nm = fmaxf(my_m, sc);
            float fct = __expf(my_m - nm);
            float we  = __expf(sc - nm);
            my_s = my_s * fct + we;
            my_m = nm;
            sfact[t] = fct; swt[t] = we;
        }
        __syncthreads();
        float fv = cur[t];
        #pragma unroll
        for (int h = 0; h < H; h++) racc[h] = racc[h] * sfact[h] + swt[h] * fv;
        buf[(e + 1) & 1][t] = pre;
        __syncthreads();
    }
    if (t < H) sfact[t] = 1.f / fmaxf(my_s, 1e-20f);
    __syncthreads();
    #pragma unroll
    for (int h = 0; h < H; h++)
        g_agg[(b * H + h) * FSZ + t] = racc[h] * sfact[h];
}

// ---------------- 5. fused dual GEMM (res + agg@W) + bias + LayerNorm ----------------
__global__ void k_rst_res(const float* __restrict__ feat, const float* __restrict__ resw,
                          const float* __restrict__ fcw, const int* __restrict__ url,
                          const float* __restrict__ bias,
                          const float* __restrict__ lg, const float* __restrict__ lb) {
    __shared__ float sF[64][33];
    __shared__ float sG[64][33];
    __shared__ float sBr[32][65];
    __shared__ float sBw[32][65];
    __shared__ int snode[64], sslot[64];
    int r0 = blockIdx.y * 64, hcol = blockIdx.x, c0 = hcol * 64;
    int t = threadIdx.x, tx = t & 15, ty = t >> 4;
    if (t < 64) {
        int n = url[r0 + t] - 1;
        snode[t] = n;
        sslot[t] = g_node_slot[n];
    }
    __syncthreads();
    float acc[4][4] = {};
    for (int k0 = 0; k0 < FSZ; k0 += 32) {
        for (int i = t; i < 64 * 32; i += 256) {
            int r = i >> 5, k = i & 31;
            sF[r][k] = feat[(long)snode[r] * FSZ + k0 + k];
            sG[r][k] = g_agg[(sslot[r] * H + hcol) * FSZ + k0 + k];
        }
        for (int i = t; i < 32 * 64; i += 256) {
            int k = i >> 6, c = i & 63;
            sBr[k][c] = resw[(k0 + k) * HD + c0 + c];
            sBw[k][c] = fcw[(k0 + k) * HD + c0 + c];
        }
        __syncthreads();
        #pragma unroll 8
        for (int kk = 0; kk < 32; kk++) {
            float af[4], ag[4], br[4], bw[4];
            #pragma unroll
            for (int j = 0; j < 4; j++) { af[j] = sF[ty * 4 + j][kk]; ag[j] = sG[ty * 4 + j][kk]; }
            #pragma unroll
            for (int i = 0; i < 4; i++) { br[i] = sBr[kk][tx * 4 + i]; bw[i] = sBw[kk][tx * 4 + i]; }
            #pragma unroll
            for (int j = 0; j < 4; j++)
                #pragma unroll
                for (int i = 0; i < 4; i++)
                    acc[j][i] += af[j] * br[i] + ag[j] * bw[i];
        }
        __syncthreads();
    }
    #pragma unroll
    for (int j = 0; j < 4; j++) {
        float s = 0.f, ss = 0.f;
        #pragma unroll
        for (int i = 0; i < 4; i++) {
            acc[j][i] += bias[c0 + tx * 4 + i];
            s += acc[j][i]; ss += acc[j][i] * acc[j][i];
        }
        #pragma unroll
        for (int o = 1; o < 16; o <<= 1) {
            s  += __shfl_xor_sync(0xffffffffu, s, o);
            ss += __shfl_xor_sync(0xffffffffu, ss, o);
        }
        float mu = s * (1.f / D), var = ss * (1.f / D) - mu * mu;
        float rs = rsqrtf(var + 1e-6f);
        #pragma unroll
        for (int i = 0; i < 4; i++) {
            int c = tx * 4 + i;
            g_x[(r0 + ty * 4 + j) * HD + c0 + c] = (acc[j][i] - mu) * rs * lg[c] + lb[c];
        }
    }
}

// ---------------- 6. fold MHA weights: M_nh = Wq Wk^T / 8,  Wvf_nh = Wv fc_w_nh ----------------
__global__ void k_fold(const float* __restrict__ wq, const float* __restrict__ wk,
                       const float* __restrict__ wv, const float* __restrict__ fcw) {
    int nh = blockIdx.x, which = blockIdx.y;
    __shared__ float sA[64][68];
    __shared__ float sB[64][68];
    int t = threadIdx.x, tx = t & 15, ty = t >> 4;
    for (int i = t; i < 64 * 64; i += 256) {
        int r = i >> 6, c = i & 63;
        sA[r][c] = which == 0 ? wq[r * HD + nh * 64 + c] : wv[r * HD + nh * 64 + c];
        if (which == 0) sB[c][r] = wk[r * HD + nh * 64 + c];      // sB[k=c][col=b]
        else            sB[r][c] = fcw[(nh * 64 + r) * D + c];    // sB[k=r][col=d]
    }
    __syncthreads();
    float acc[4][4] = {};
    #pragma unroll 8
    for (int k = 0; k < 64; k++) {
        float a[4], bb[4];
        #pragma unroll
        for (int j = 0; j < 4; j++) a[j] = sA[ty * 4 + j][k];
        #pragma unroll
        for (int i = 0; i < 4; i++) bb[i] = sB[k][tx * 4 + i];
        #pragma unroll
        for (int j = 0; j < 4; j++)
            #pragma unroll
            for (int i = 0; i < 4; i++)
                acc[j][i] += a[j] * bb[i];
    }
    int base = which == 0 ? nh * 64 : 512 + nh * 64;
    float scale = which == 0 ? 0.125f : 1.f;
    #pragma unroll
    for (int j = 0; j < 4; j++)
        #pragma unroll
        for (int i = 0; i < 4; i++)
            g_MZ[(ty * 4 + j) * 1024 + base + tx * 4 + i] = acc[j][i] * scale;
}

// ---------------- 7. yz GEMM: [8192,64] x [64,1024] ----------------
__global__ void k_yz() {
    __shared__ float sA[64][68];   // [k][r], 272B rows -> LDS.128-able
    __shared__ float sB[64][68];   // [k][c]
    int r0 = blockIdx.y * 64, c0 = blockIdx.x * 64;
    int t = threadIdx.x, tx = t & 15, ty = t >> 4;
    for (int i = t; i < 64 * 64; i += 256) {
        int r = i >> 6, k = i & 63;
        sA[k][r] = g_x[(r0 + r) * D + k];
    }
    for (int i = t; i < 64 * 64; i += 256) {
        int k = i >> 6, c = i & 63;
        sB[k][c] = g_MZ[k * 1024 + c0 + c];
    }
    __syncthreads();
    float acc[4][4] = {};
    #pragma unroll 8
    for (int k = 0; k < 64; k++) {
        float a[4], bb[4];
        #pragma unroll
        for (int j = 0; j < 4; j++) a[j] = sA[k][ty * 4 + j];
        #pragma unroll
        for (int i = 0; i < 4; i++) bb[i] = sB[k][tx * 4 + i];
        #pragma unroll
        for (int j = 0; j < 4; j++)
            #pragma unroll
            for (int i = 0; i < 4; i++)
                acc[j][i] += a[j] * bb[i];
    }
    #pragma unroll
    for (int j = 0; j < 4; j++)
        #pragma unroll
        for (int i = 0; i < 4; i++)
            g_yz[(long)(r0 + ty * 4 + j) * 1024 + c0 + tx * 4 + i] = acc[j][i];
}

// ---------------- 8. fused per-b epilogue ----------------
__global__ void k_attn_final(const float* __restrict__ fcb,
                             const float* __restrict__ mlg, const float* __restrict__ mlb,
                             const float* __restrict__ ow,  const float* __restrict__ ob,
                             float* __restrict__ out) {
    int b = blockIdx.x, t = threadIdx.x, lane = t & 31, w = t >> 5;   // w = nh
    __shared__ float sx[8][68];
    __shared__ float sy[8][8][68];    // [nh][qi][d]
    __shared__ float sat[NH][8][9];
    __shared__ float sout[NH][8][72];
    __shared__ float sred[8][68];
    __shared__ float spool[64];
    const float* xb = g_x + (long)b * HD;
    const float* yz = g_yz + (long)b * 8 * 1024;
    for (int i = t; i < 128; i += 256) {
        int r = i >> 4, c4 = (i & 15) * 4;
        *(float4*)&sx[r][c4] = *(const float4*)&xb[r * 64 + c4];
    }
    for (int j = lane; j < 128; j += 32) {
        int r = j >> 4, c4 = (j & 15) * 4;
        *(float4*)&sy[w][r][c4] = *(const float4*)&yz[r * 1024 + w * 64 + c4];
    }
    __syncthreads();
    // scores[qi][ki] = y_nh[qi] . x[ki]   (1/sqrt(dk) folded into M)
    #pragma unroll
    for (int pp = 0; pp < 2; pp++) {
        int p = lane + pp * 32, qi = p >> 3, ki = p & 7;
        float a = 0.f;
        #pragma unroll
        for (int d = 0; d < 64; d++) a += sy[w][qi][d] * sx[ki][d];
        sat[w][qi][ki] = a;
    }
    __syncwarp();
    if (lane < 8) {
        float mx = -1e30f;
        #pragma unroll
        for (int k2 = 0; k2 < 8; k2++) mx = fmaxf(mx, sat[w][lane][k2]);
        float s = 0.f;
        #pragma unroll
        for (int k2 = 0; k2 < 8; k2++) { float e = __expf(sat[w][lane][k2] - mx); s += e; sat[w][lane][k2] = e; }
        float inv = 1.f / s;
        #pragma unroll
        for (int k2 = 0; k2 < 8; k2++) sat[w][lane][k2] *= inv;
    }
    __syncwarp();
    // partial out for this nh: attn_nh @ z_nh
    #pragma unroll
    for (int pp = 0; pp < 2; pp++) {
        int d = lane + pp * 32;
        float vk[8];
        #pragma unroll
        for (int k2 = 0; k2 < 8; k2++) vk[k2] = yz[k2 * 1024 + 512 + w * 64 + d];
        #pragma unroll
        for (int qi = 0; qi < 8; qi++) {
            float a = 0.f;
            #pragma unroll
            for (int k2 = 0; k2 < 8; k2++) a += sat[w][qi][k2] * vk[k2];
            sout[w][qi][d] = a;
        }
    }
    __syncthreads();
    // reduce over nh + fc bias + residual
    for (int i = t; i < 512; i += 256) {
        int qi = i >> 6, d = i & 63;
        float r = sx[qi][d] + fcb[d];
        #pragma unroll
        for (int w2 = 0; w2 < NH; w2++) r += sout[w2][qi][d];
        sred[qi][d] = r;
    }
    __syncthreads();
    // LN row w by warp w
    {
        float v0 = sred[w][lane], v1 = sred[w][lane + 32];
        float s = v0 + v1, ss = v0 * v0 + v1 * v1;
        #pragma unroll
        for (int o = 16; o; o >>= 1) {
            s  += __shfl_xor_sync(0xffffffffu, s, o);
            ss += __shfl_xor_sync(0xffffffffu, ss, o);
        }
        float mu = s * (1.f / D), var = ss * (1.f / D) - mu * mu;
        float rs = rsqrtf(var + 1e-6f);
        sred[w][lane]      = (v0 - mu) * rs * mlg[lane] + mlb[lane];
        sred[w][lane + 32] = (v1 - mu) * rs * mlg[lane + 32] + mlb[lane + 32];
    }
    __syncthreads();
    if (t < 64) {
        float p = 0.f;
        #pragma unroll
        for (int s2 = 0; s2 < 8; s2++) p += sred[s2][t];
        spool[t] = p;
    }
    __syncthreads();
    if (t < 2) {
        float a = ob[t];
        #pragma unroll 8
        for (int d = 0; d < D; d++) a += spool[d] * ow[d * 2 + t];
        out[b * 2 + t] = a;
    }
}

// ---------------- launch ----------------
extern "C" void kernel_launch(void* const* d_in, const int* in_sizes, int n_in,
                              void* d_out, int out_size) {
    const float* features  = (const float*)d_in[0];
    const int*   src       = (const int*)  d_in[1];
    const int*   dst       = (const int*)  d_in[2];
    const int*   url       = (const int*)  d_in[3];
    const float* gat_fc_w  = (const float*)d_in[4];
    const float* attn_l    = (const float*)d_in[5];
    const float* attn_r    = (const float*)d_in[6];
    const float* gat_res_w = (const float*)d_in[7];
    const float* gat_bias  = (const float*)d_in[8];
    const float* ln_g      = (const float*)d_in[9];
    const float* ln_b      = (const float*)d_in[10];
    const float* wq        = (const float*)d_in[11];
    const float* wk        = (const float*)d_in[12];
    const float* wv        = (const float*)d_in[13];
    const float* fc_w      = (const float*)d_in[14];
    const float* fc_b      = (const float*)d_in[15];
    const float* mha_ln_g  = (const float*)d_in[16];
    const float* mha_ln_b  = (const float*)d_in[17];
    const float* out_w     = (const float*)d_in[18];
    const float* out_b     = (const float*)d_in[19];
    float* out = (float*)d_out;

    k_init<<<(N_NODES + 255) / 256, 256>>>(gat_fc_w, attn_l, attn_r);
    k_scatter<<<4, 256>>>(url);
    k_filter<<<(E_EDGES / 4 + 255) / 256, 256>>>(src, dst);
    k_gat<<<BSZ, 256>>>(features, url);
    k_fold<<<dim3(NH, 2), 256>>>(wq, wk, wv, fc_w);
    k_rst_res<<<dim3(8, BSZ / 64), 256>>>(features, gat_res_w, gat_fc_w, url,
                                          gat_bias, ln_g, ln_b);
    k_yz<<<dim3(16, 128), 256>>>();
    k_attn_final<<<BSZ, 256>>>(fc_b, mha_ln_g, mha_ln_b, out_w, out_b, out);
}

// round 6
// speedup vs baseline: 2.5518x; 1.0713x over previous
#include <cuda_runtime.h>
#include <math.h>
#include <stdint.h>

#define N_NODES 50000
#define E_EDGES 400000
#define FSZ 256
#define H 8
#define D 64
#define HD 512
#define BSZ 1024
#define NH 8
#define DEG 64          // per-slot edge cap (Poisson(8); P(>64) ~ 1e-30)

// ---------------- scratch ----------------
__device__ int   g_node_slot[N_NODES];
__device__ int   g_slot_cnt[BSZ];
__device__ int   g_bsrc[BSZ * DEG];
__device__ float g_WL[H * FSZ];          // [h][f]
__device__ float g_WR[H * FSZ];          // [h][f]
__device__ float g_agg[BSZ * H * FSZ];   // softmax-weighted raw-feature sums per (slot, head)
__device__ float g_x[BSZ * HD];          // post-LN GAT output == [8192][64] rows (b*8+s)
__device__ float g_MZ[D * 1024];         // [k][ 0..511 = Wq Wk^T/8, 512..1023 = Wv fc_w ]
__device__ float g_yz[BSZ * 8 * 1024];   // per row: y | z

// ---------------- f32x2 packed FMA helpers ----------------
__device__ __forceinline__ uint64_t packf2(float x, float y) {
    uint64_t r;
    asm("mov.b64 %0, {%1, %2};" : "=l"(r) : "r"(__float_as_uint(x)), "r"(__float_as_uint(y)));
    return r;
}
__device__ __forceinline__ uint64_t packf2s(float x) { return packf2(x, x); }
__device__ __forceinline__ void ffma2(uint64_t& d, uint64_t a, uint64_t b) {
    asm("fma.rn.f32x2 %0, %1, %2, %0;" : "+l"(d) : "l"(a), "l"(b));
}
__device__ __forceinline__ float2 unpackf2(uint64_t v) {
    uint32_t lo, hi;
    asm("mov.b64 {%0, %1}, %2;" : "=r"(lo), "=r"(hi) : "l"(v));
    return make_float2(__uint_as_float(lo), __uint_as_float(hi));
}

// ---------------- 1. init scratch + fold GAT attn vecs + fold MHA weights ----------------
// blocks [0, 196): init + WL/WR fold.  blocks [196, 212): MHA weight fold.
__global__ void k_initfold(const float* __restrict__ fcw_gat,
                           const float* __restrict__ al,
                           const float* __restrict__ ar,
                           const float* __restrict__ wq, const float* __restrict__ wk,
                           const float* __restrict__ wv, const float* __restrict__ fcw) {
    if (blockIdx.x < 196) {
        int i = blockIdx.x * blockDim.x + threadIdx.x;
        if (i < N_NODES) g_node_slot[i] = 0x7fffffff;
        if (i < BSZ) g_slot_cnt[i] = 0;
        if (i < FSZ * H) {
            int f = i >> 3, h = i & 7;
            float wl = 0.f, wr = 0.f;
            #pragma unroll 8
            for (int d = 0; d < D; d++) {
                float w = fcw_gat[f * HD + h * D + d];
                wl += w * al[h * D + d];
                wr += w * ar[h * D + d];
            }
            g_WL[h * FSZ + f] = wl;
            g_WR[h * FSZ + f] = wr;
        }
        return;
    }
    // ---- MHA fold: M_nh = Wq Wk^T / 8 ; Wvf_nh = Wv fc_w_nh ----
    int fb = blockIdx.x - 196;
    int nh = fb >> 1, which = fb & 1;
    __shared__ float sA[64][68];
    __shared__ float sB[64][68];
    int t = threadIdx.x, tx = t & 15, ty = t >> 4;
    for (int i = t; i < 64 * 64; i += 256) {
        int r = i >> 6, c = i & 63;
        sA[r][c] = which == 0 ? wq[r * HD + nh * 64 + c] : wv[r * HD + nh * 64 + c];
        if (which == 0) sB[c][r] = wk[r * HD + nh * 64 + c];      // sB[k=c][col=b]
        else            sB[r][c] = fcw[(nh * 64 + r) * D + c];    // sB[k=r][col=d]
    }
    __syncthreads();
    float acc[4][4] = {};
    #pragma unroll 8
    for (int k = 0; k < 64; k++) {
        float a[4], bb[4];
        #pragma unroll
        for (int j = 0; j < 4; j++) a[j] = sA[ty * 4 + j][k];
        #pragma unroll
        for (int i = 0; i < 4; i++) bb[i] = sB[k][tx * 4 + i];
        #pragma unroll
        for (int j = 0; j < 4; j++)
            #pragma unroll
            for (int i = 0; i < 4; i++)
                acc[j][i] += a[j] * bb[i];
    }
    int base = which == 0 ? nh * 64 : 512 + nh * 64;
    float scale = which == 0 ? 0.125f : 1.f;
    #pragma unroll
    for (int j = 0; j < 4; j++)
        #pragma unroll
        for (int i = 0; i < 4; i++)
            g_MZ[(ty * 4 + j) * 1024 + base + tx * 4 + i] = acc[j][i] * scale;
}

// ---------------- 2. mark selected nodes ----------------
__global__ void k_scatter(const int* __restrict__ url) {
    int b = blockIdx.x * blockDim.x + threadIdx.x;
    if (b < BSZ) atomicMin(&g_node_slot[url[b] - 1], b);
}

// ---------------- 3. bucket edges by destination slot (2x int4 per thread) ----------------
__global__ void k_filter(const int* __restrict__ src, const int* __restrict__ dst) {
    int base = (blockIdx.x * blockDim.x + threadIdx.x) * 2;
    if (base >= E_EDGES / 4) return;
    int4 dv0 = ((const int4*)dst)[base];
    int4 dv1 = ((const int4*)dst)[base + 1];
    int4 sv0 = ((const int4*)src)[base];
    int4 sv1 = ((const int4*)src)[base + 1];
    int d[8]  = {dv0.x, dv0.y, dv0.z, dv0.w, dv1.x, dv1.y, dv1.z, dv1.w};
    int s8[8] = {sv0.x, sv0.y, sv0.z, sv0.w, sv1.x, sv1.y, sv1.z, sv1.w};
    int sl[8];
    #pragma unroll
    for (int j = 0; j < 8; j++) sl[j] = g_node_slot[d[j]];
    #pragma unroll
    for (int j = 0; j < 8; j++) {
        if (sl[j] != 0x7fffffff) {
            int pos = atomicAdd(&g_slot_cnt[sl[j]], 1);
            if (pos < DEG) g_bsrc[sl[j] * DEG + pos] = s8[j];
        }
    }
}

// ---------------- 4. GAT aggregation: edge-parallel scores, 3 syncs total ----------------
__global__ void k_gat(const float* __restrict__ feat, const int* __restrict__ url) {
    int b = blockIdx.x, t = threadIdx.x, lane = t & 31, w = t >> 5;
    __shared__ float sWL[H * FSZ];
    __shared__ float sWR[H * FSZ];
    __shared__ float sdst[FSZ];
    __shared__ float ser[H];
    __shared__ float sw[DEG][H];
    __shared__ int   ssrc[DEG];

    int cnt = g_slot_cnt[b]; if (cnt > DEG) cnt = DEG;
    for (int i = t; i < H * FSZ; i += 256) { sWL[i] = g_WL[i]; sWR[i] = g_WR[i]; }
    sdst[t] = feat[(long)(url[b] - 1) * FSZ + t];
    if (t < cnt) ssrc[t] = g_bsrc[b * DEG + t];
    __syncthreads();

    // er[h]: warp w computes head w
    {
        float a = 0.f;
        #pragma unroll
        for (int j = 0; j < 8; j++) a += sdst[lane + 32 * j] * sWR[w * FSZ + lane + 32 * j];
        #pragma unroll
        for (int o = 16; o; o >>= 1) a += __shfl_xor_sync(0xffffffffu, a, o);
        if (lane == 0) ser[w] = a;
    }
    __syncthreads();

    // scores: warp per edge, ALL heads per warp, no syncs
    for (int e = w; e < cnt; e += 8) {
        const float* F = feat + (long)ssrc[e] * FSZ;
        float fv[8];
        #pragma unroll
        for (int j = 0; j < 8; j++) fv[j] = F[lane + 32 * j];
        float acc[8];
        #pragma unroll
        for (int h = 0; h < 8; h++) {
            float a = 0.f;
            #pragma unroll
            for (int j = 0; j < 8; j++) a += fv[j] * sWL[h * FSZ + lane + 32 * j];
            acc[h] = a;
        }
        #pragma unroll
        for (int o = 16; o; o >>= 1)
            #pragma unroll
            for (int h = 0; h < 8; h++)
                acc[h] += __shfl_xor_sync(0xffffffffu, acc[h], o);
        if (lane == 0) {
            #pragma unroll
            for (int h = 0; h < 8; h++) {
                float s = acc[h] + ser[h];
                sw[e][h] = s > 0.f ? s : 0.2f * s;
            }
        }
    }
    __syncthreads();

    // softmax per head (8 owner threads)
    if (t < H) {
        float mx = -1e30f;
        for (int e = 0; e < cnt; e++) mx = fmaxf(mx, sw[e][t]);
        float sum = 0.f;
        for (int e = 0; e < cnt; e++) { float ex = __expf(sw[e][t] - mx); sum += ex; sw[e][t] = ex; }
        float inv = 1.f / fmaxf(sum, 1e-20f);
        for (int e = 0; e < cnt; e++) sw[e][t] *= inv;
    }
    __syncthreads();

    // aggregation: thread t owns feature col t; rows hot in L2 from score phase
    float racc[H] = {};
    int e = 0;
    for (; e + 1 < cnt; e += 2) {
        float f0 = feat[(long)ssrc[e] * FSZ + t];
        float f1 = feat[(long)ssrc[e + 1] * FSZ + t];
        #pragma unroll
        for (int h = 0; h < 8; h++) racc[h] += sw[e][h] * f0 + sw[e + 1][h] * f1;
    }
    if (e < cnt) {
        float f0 = feat[(long)ssrc[e] * FSZ + t];
        #pragma unroll
        for (int h = 0; h < 8; h++) racc[h] += sw[e][h] * f0;
    }
    #pragma unroll
    for (int h = 0; h < 8; h++)
        g_agg[(b * H + h) * FSZ + t] = racc[h];
}

// ---------------- 5. fused dual GEMM (res + agg@W) + bias + LayerNorm (FFMA2) ----------------
__global__ void k_rst_res(const float* __restrict__ feat, const float* __restrict__ resw,
                          const float* __restrict__ fcw, const int* __restrict__ url,
                          const float* __restrict__ bias,
                          const float* __restrict__ lg, const float* __restrict__ lb) {
    __shared__ float sF[32][72];     // [k][r] transposed
    __shared__ float sG[32][72];
    __shared__ float sBr[32][68];
    __shared__ float sBw[32][68];
    __shared__ int snode[64], sslot[64];
    int r0 = blockIdx.y * 64, hcol = blockIdx.x, c0 = hcol * 64;
    int t = threadIdx.x, tx = t & 15, ty = t >> 4;
    if (t < 64) {
        int n = url[r0 + t] - 1;
        snode[t] = n;
        sslot[t] = g_node_slot[n];
    }
    __syncthreads();
    uint64_t acc2[4][2] = {};
    for (int k0 = 0; k0 < FSZ; k0 += 32) {
        for (int i = t; i < 64 * 32; i += 256) {
            int k = i & 31, r = i >> 5;
            sF[k][r] = feat[(long)snode[r] * FSZ + k0 + k];
            sG[k][r] = g_agg[(sslot[r] * H + hcol) * FSZ + k0 + k];
        }
        for (int i = t; i < 32 * 64; i += 256) {
            int k = i >> 6, c = i & 63;
            sBr[k][c] = resw[(k0 + k) * HD + c0 + c];
            sBw[k][c] = fcw[(k0 + k) * HD + c0 + c];
        }
        __syncthreads();
        #pragma unroll 4
        for (int kk = 0; kk < 32; kk++) {
            float4 af = *(const float4*)&sF[kk][ty * 4];
            float4 ag = *(const float4*)&sG[kk][ty * 4];
            float4 brv = *(const float4*)&sBr[kk][tx * 4];
            float4 bwv = *(const float4*)&sBw[kk][tx * 4];
            uint64_t br2[2] = { packf2(brv.x, brv.y), packf2(brv.z, brv.w) };
            uint64_t bw2[2] = { packf2(bwv.x, bwv.y), packf2(bwv.z, bwv.w) };
            float afv[4] = {af.x, af.y, af.z, af.w};
            float agv[4] = {ag.x, ag.y, ag.z, ag.w};
            #pragma unroll
            for (int j = 0; j < 4; j++) {
                uint64_t a2 = packf2s(afv[j]);
                uint64_t g2 = packf2s(agv[j]);
                ffma2(acc2[j][0], a2, br2[0]);
                ffma2(acc2[j][1], a2, br2[1]);
                ffma2(acc2[j][0], g2, bw2[0]);
                ffma2(acc2[j][1], g2, bw2[1]);
            }
        }
        __syncthreads();
    }
    #pragma unroll
    for (int j = 0; j < 4; j++) {
        float2 lo = unpackf2(acc2[j][0]), hi = unpackf2(acc2[j][1]);
        float acc[4] = {lo.x, lo.y, hi.x, hi.y};
        float s = 0.f, ss = 0.f;
        #pragma unroll
        for (int i = 0; i < 4; i++) {
            acc[i] += bias[c0 + tx * 4 + i];
            s += acc[i]; ss += acc[i] * acc[i];
        }
        #pragma unroll
        for (int o = 1; o < 16; o <<= 1) {
            s  += __shfl_xor_sync(0xffffffffu, s, o);
            ss += __shfl_xor_sync(0xffffffffu, ss, o);
        }
        float mu = s * (1.f / D), var = ss * (1.f / D) - mu * mu;
        float rs = rsqrtf(var + 1e-6f);
        #pragma unroll
        for (int i = 0; i < 4; i++) {
            int c = tx * 4 + i;
            g_x[(r0 + ty * 4 + j) * HD + c0 + c] = (acc[i] - mu) * rs * lg[c] + lb[c];
        }
    }
}

// ---------------- 6. yz GEMM: [8192,64] x [64,1024] (FFMA2, transposed A) ----------------
__global__ void k_yz() {
    __shared__ float sA[64][72];   // [k][r]
    __shared__ float sB[64][68];   // [k][c]
    int r0 = blockIdx.y * 64, c0 = blockIdx.x * 64;
    int t = threadIdx.x, tx = t & 15, ty = t >> 4;
    for (int i = t; i < 64 * 64; i += 256) {
        int k = i & 63, r = i >> 6;
        sA[k][r] = g_x[(r0 + r) * D + k];
    }
    for (int i = t; i < 64 * 64; i += 256) {
        int k = i >> 6, c = i & 63;
        sB[k][c] = g_MZ[k * 1024 + c0 + c];
    }
    __syncthreads();
    uint64_t acc2[4][2] = {};
    #pragma unroll 8
    for (int k = 0; k < 64; k++) {
        float4 a4 = *(const float4*)&sA[k][ty * 4];
        float4 b4 = *(const float4*)&sB[k][tx * 4];
        uint64_t b2[2] = { packf2(b4.x, b4.y), packf2(b4.z, b4.w) };
        float av[4] = {a4.x, a4.y, a4.z, a4.w};
        #pragma unroll
        for (int j = 0; j < 4; j++) {
            uint64_t aj = packf2s(av[j]);
            ffma2(acc2[j][0], aj, b2[0]);
            ffma2(acc2[j][1], aj, b2[1]);
        }
    }
    #pragma unroll
    for (int j = 0; j < 4; j++) {
        float2 lo = unpackf2(acc2[j][0]), hi = unpackf2(acc2[j][1]);
        float4 o4 = make_float4(lo.x, lo.y, hi.x, hi.y);
        *(float4*)&g_yz[(long)(r0 + ty * 4 + j) * 1024 + c0 + tx * 4] = o4;
    }
}

// ---------------- 7. fused per-b epilogue ----------------
__global__ void k_attn_final(const float* __restrict__ fcb,
                             const float* __restrict__ mlg, const float* __restrict__ mlb,
                             const float* __restrict__ ow,  const float* __restrict__ ob,
                             float* __restrict__ out) {
    int b = blockIdx.x, t = threadIdx.x, lane = t & 31, w = t >> 5;   // w = nh
    __shared__ float sx[8][68];
    __shared__ float sy[8][8][68];    // [nh][qi][d]
    __shared__ float sat[NH][8][9];
    __shared__ float sout[NH][8][72];
    __shared__ float sred[8][68];
    __shared__ float spool[64];
    const float* xb = g_x + (long)b * HD;
    const float* yz = g_yz + (long)b * 8 * 1024;
    for (int i = t; i < 128; i += 256) {
        int r = i >> 4, c4 = (i & 15) * 4;
        *(float4*)&sx[r][c4] = *(const float4*)&xb[r * 64 + c4];
    }
    for (int j = lane; j < 128; j += 32) {
        int r = j >> 4, c4 = (j & 15) * 4;
        *(float4*)&sy[w][r][c4] = *(const float4*)&yz[r * 1024 + w * 64 + c4];
    }
    __syncthreads();
    #pragma unroll
    for (int pp = 0; pp < 2; pp++) {
        int p = lane + pp * 32, qi = p >> 3, ki = p & 7;
        float a = 0.f;
        #pragma unroll
        for (int d = 0; d < 64; d++) a += sy[w][qi][d] * sx[ki][d];
        sat[w][qi][ki] = a;
    }
    __syncwarp();
    if (lane < 8) {
        float mx = -1e30f;
        #pragma unroll
        for (int k2 = 0; k2 < 8; k2++) mx = fmaxf(mx, sat[w][lane][k2]);
        float s = 0.f;
        #pragma unroll
        for (int k2 = 0; k2 < 8; k2++) { float e = __expf(sat[w][lane][k2] - mx); s += e; sat[w][lane][k2] = e; }
        float inv = 1.f / s;
        #pragma unroll
        for (int k2 = 0; k2 < 8; k2++) sat[w][lane][k2] *= inv;
    }
    __syncwarp();
    #pragma unroll
    for (int pp = 0; pp < 2; pp++) {
        int d = lane + pp * 32;
        float vk[8];
        #pragma unroll
        for (int k2 = 0; k2 < 8; k2++) vk[k2] = yz[k2 * 1024 + 512 + w * 64 + d];
        #pragma unroll
        for (int qi = 0; qi < 8; qi++) {
            float a = 0.f;
            #pragma unroll
            for (int k2 = 0; k2 < 8; k2++) a += sat[w][qi][k2] * vk[k2];
            sout[w][qi][d] = a;
        }
    }
    __syncthreads();
    for (int i = t; i < 512; i += 256) {
        int qi = i >> 6, d = i & 63;
        float r = sx[qi][d] + fcb[d];
        #pragma unroll
        for (int w2 = 0; w2 < NH; w2++) r += sout[w2][qi][d];
        sred[qi][d] = r;
    }
    __syncthreads();
    {
        float v0 = sred[w][lane], v1 = sred[w][lane + 32];
        float s = v0 + v1, ss = v0 * v0 + v1 * v1;
        #pragma unroll
        for (int o = 16; o; o >>= 1) {
            s  += __shfl_xor_sync(0xffffffffu, s, o);
            ss += __shfl_xor_sync(0xffffffffu, ss, o);
        }
        float mu = s * (1.f / D), var = ss * (1.f / D) - mu * mu;
        float rs = rsqrtf(var + 1e-6f);
        sred[w][lane]      = (v0 - mu) * rs * mlg[lane] + mlb[lane];
        sred[w][lane + 32] = (v1 - mu) * rs * mlg[lane + 32] + mlb[lane + 32];
    }
    __syncthreads();
    if (t < 64) {
        float p = 0.f;
        #pragma unroll
        for (int s2 = 0; s2 < 8; s2++) p += sred[s2][t];
        spool[t] = p;
    }
    __syncthreads();
    if (t < 2) {
        float a = ob[t];
        #pragma unroll 8
        for (int d = 0; d < D; d++) a += spool[d] * ow[d * 2 + t];
        out[b * 2 + t] = a;
    }
}

// ---------------- launch ----------------
extern "C" void kernel_launch(void* const* d_in, const int* in_sizes, int n_in,
                              void* d_out, int out_size) {
    const float* features  = (const float*)d_in[0];
    const int*   src       = (const int*)  d_in[1];
    const int*   dst       = (const int*)  d_in[2];
    const int*   url       = (const int*)  d_in[3];
    const float* gat_fc_w  = (const float*)d_in[4];
    const float* attn_l    = (const float*)d_in[5];
    const float* attn_r    = (const float*)d_in[6];
    const float* gat_res_w = (const float*)d_in[7];
    const float* gat_bias  = (const float*)d_in[8];
    const float* ln_g      = (const float*)d_in[9];
    const float* ln_b      = (const float*)d_in[10];
    const float* wq        = (const float*)d_in[11];
    const float* wk        = (const float*)d_in[12];
    const float* wv        = (const float*)d_in[13];
    const float* fc_w      = (const float*)d_in[14];
    const float* fc_b      = (const float*)d_in[15];
    const float* mha_ln_g  = (const float*)d_in[16];
    const float* mha_ln_b  = (const float*)d_in[17];
    const float* out_w     = (const float*)d_in[18];
    const float* out_b     = (const float*)d_in[19];
    float* out = (float*)d_out;

    k_initfold<<<212, 256>>>(gat_fc_w, attn_l, attn_r, wq, wk, wv, fc_w);
    k_scatter<<<4, 256>>>(url);
    k_filter<<<196, 256>>>(src, dst);
    k_gat<<<BSZ, 256>>>(features, url);
    k_rst_res<<<dim3(8, BSZ / 64), 256>>>(features, gat_res_w, gat_fc_w, url,
                                          gat_bias, ln_g, ln_b);
    k_yz<<<dim3(16, 128), 256>>>();
    k_attn_final<<<BSZ, 256>>>(fc_b, mha_ln_g, mha_ln_b, out_w, out_b, out);
}